// round 3
// baseline (speedup 1.0000x reference)
#include <cuda_runtime.h>
#include <math.h>

#define MAXN 400000
#define TPB  128
#define ROWSTRIDE 132           // 128 floats + 16B pad, keeps float4 alignment
#define XS_BYTES (TPB * ROWSTRIDE * 4)

// Accumulators: [0..3]=S0(k)  [4..15]=S1(k*3+d)  [16..39]=S2(k*6+m)  [40]=loss1  [41]=esum
__device__ double g_acc[42];
__device__ float  g_z[3 * MAXN];          // planar: z1 | cos | euc

__device__ __forceinline__ float tanh_f(float x) {
    float y = fminf(fmaxf(x, -8.f), 8.f);
    float e = __expf(2.f * y);
    return __fdividef(e - 1.f, e + 1.f);
}

__device__ __forceinline__ float wsum(float v) {
#pragma unroll
    for (int o = 16; o; o >>= 1) v += __shfl_down_sync(0xffffffffu, v, o);
    return v;
}

__global__ void zero_kernel() {
    int t = threadIdx.x;
    if (t < 42) g_acc[t] = 0.0;
}

__global__ void __launch_bounds__(TPB) fwd_kernel(
    const float* __restrict__ x1,
    const float* __restrict__ ew1, const float* __restrict__ eb1,
    const float* __restrict__ ew2, const float* __restrict__ eb2,
    const float* __restrict__ ew3, const float* __restrict__ eb3,
    const float* __restrict__ dw1, const float* __restrict__ db1,
    const float* __restrict__ dw2, const float* __restrict__ db2,
    const float* __restrict__ dw3, const float* __restrict__ db3,
    const float* __restrict__ tw1, const float* __restrict__ tb1,
    const float* __restrict__ tw2, const float* __restrict__ tb2,
    int n)
{
    extern __shared__ __align__(16) float xs[];   // [TPB][ROWSTRIDE]

    __shared__ __align__(16) float sW1[2048];
    __shared__ __align__(16) float sB1[16];
    __shared__ __align__(16) float sW2[128];
    __shared__ __align__(16) float sB2[8];
    __shared__ __align__(16) float sW3[8];
    __shared__ __align__(16) float sB3[4];
    __shared__ __align__(16) float sDW1[8];
    __shared__ __align__(16) float sDB1[8];
    __shared__ __align__(16) float sDW2[128];
    __shared__ __align__(16) float sDB2[16];
    __shared__ __align__(16) float sDW3T[2048];   // transposed: [j][i]
    __shared__ __align__(16) float sDB3[128];
    __shared__ __align__(16) float sTW1[24];
    __shared__ __align__(16) float sTB1[8];
    __shared__ __align__(16) float sTW2[32];
    __shared__ __align__(16) float sTB2[4];
    __shared__ float sRed[4][41];

    const int tid = threadIdx.x;

    // -------- stage weights --------
    for (int i = tid; i < 2048; i += TPB) sW1[i] = ew1[i];
    for (int i = tid; i < 2048; i += TPB) { int r = i >> 7, j = i & 127; sDW3T[j * 16 + r] = dw3[i]; }
    if (tid < 16)  sB1[tid] = eb1[tid];
    for (int i = tid; i < 128; i += TPB) sW2[i]  = ew2[i];
    for (int i = tid; i < 128; i += TPB) sDW2[i] = dw2[i];
    for (int i = tid; i < 128; i += TPB) sDB3[i] = db3[i];
    if (tid < 8)  { sB2[tid] = eb2[tid]; sW3[tid] = ew3[tid]; sDW1[tid] = dw1[tid]; sDB1[tid] = db1[tid]; sTB1[tid] = tb1[tid]; }
    if (tid < 16) sDB2[tid] = db2[tid];
    if (tid < 24) sTW1[tid] = tw1[tid];
    if (tid < 32) sTW2[tid] = tw2[tid];
    if (tid < 4)  sTB2[tid] = tb2[tid];
    if (tid == 0) sB3[0] = eb3[0];

    // -------- stage x tile (coalesced) --------
    const int row0 = blockIdx.x * TPB;
#pragma unroll 4
    for (int i = tid; i < TPB * 32; i += TPB) {
        int r  = i >> 5;
        int c4 = i & 31;
        int gr = row0 + r;
        if (gr >= n) gr = 0;
        float4 v = ((const float4*)(x1 + (size_t)gr * 128))[c4];
        *(float4*)&xs[r * ROWSTRIDE + c4 * 4] = v;
    }
    __syncthreads();

    const int   row   = row0 + tid;
    const float validf = (row < n) ? 1.f : 0.f;
    const float* xrow = &xs[tid * ROWSTRIDE];

    // ---------------- encoder layer 1 (128->16) + ||x1||^2 ----------------
    float acc[16];
#pragma unroll
    for (int j = 0; j < 16; j++) acc[j] = sB1[j];
    float n1 = 0.f;

#pragma unroll 2
    for (int c = 0; c < 32; c++) {
        float4 v = *(const float4*)&xrow[c * 4];
        n1 = fmaf(v.x, v.x, fmaf(v.y, v.y, fmaf(v.z, v.z, fmaf(v.w, v.w, n1))));
        const float4* wr = (const float4*)&sW1[c * 64];
#pragma unroll
        for (int r = 0; r < 4; r++) {
            float xv = (r == 0) ? v.x : (r == 1) ? v.y : (r == 2) ? v.z : v.w;
            float4 w0 = wr[r * 4 + 0], w1 = wr[r * 4 + 1];
            float4 w2 = wr[r * 4 + 2], w3 = wr[r * 4 + 3];
            acc[0]  = fmaf(xv, w0.x, acc[0]);
            acc[1]  = fmaf(xv, w0.y, acc[1]);
            acc[2]  = fmaf(xv, w0.z, acc[2]);
            acc[3]  = fmaf(xv, w0.w, acc[3]);
            acc[4]  = fmaf(xv, w1.x, acc[4]);
            acc[5]  = fmaf(xv, w1.y, acc[5]);
            acc[6]  = fmaf(xv, w1.z, acc[6]);
            acc[7]  = fmaf(xv, w1.w, acc[7]);
            acc[8]  = fmaf(xv, w2.x, acc[8]);
            acc[9]  = fmaf(xv, w2.y, acc[9]);
            acc[10] = fmaf(xv, w2.z, acc[10]);
            acc[11] = fmaf(xv, w2.w, acc[11]);
            acc[12] = fmaf(xv, w3.x, acc[12]);
            acc[13] = fmaf(xv, w3.y, acc[13]);
            acc[14] = fmaf(xv, w3.z, acc[14]);
            acc[15] = fmaf(xv, w3.w, acc[15]);
        }
    }

    float h1[16];
#pragma unroll
    for (int j = 0; j < 16; j++) h1[j] = tanh_f(acc[j]);

    // ---------------- encoder layer 2 (16->8) ----------------
    float h2[8];
#pragma unroll
    for (int j = 0; j < 8; j++) {
        float t = sB2[j];
#pragma unroll
        for (int i = 0; i < 16; i++) t = fmaf(h1[i], sW2[i * 8 + j], t);
        h2[j] = tanh_f(t);
    }

    // ---------------- encoder layer 3 (8->1) ----------------
    float z1v;
    {
        float t = sB3[0];
#pragma unroll
        for (int i = 0; i < 8; i++) t = fmaf(h2[i], sW3[i], t);
        z1v = tanh_f(t);
    }

    // ---------------- decoder layer 1 (1->8) ----------------
    float d1[8];
#pragma unroll
    for (int j = 0; j < 8; j++) d1[j] = tanh_f(fmaf(z1v, sDW1[j], sDB1[j]));

    // ---------------- decoder layer 2 (8->16) ----------------
    float d2[16];
#pragma unroll
    for (int j = 0; j < 16; j++) {
        float t = sDB2[j];
#pragma unroll
        for (int i = 0; i < 8; i++) t = fmaf(d1[i], sDW2[i * 16 + j], t);
        d2[j] = tanh_f(t);
    }

    // ---------------- decoder layer 3 (16->128) + distances ----------------
    float dotv = 0.f, n2 = 0.f, e2 = 0.f;
#pragma unroll 2
    for (int c = 0; c < 32; c++) {
        float4 xv = *(const float4*)&xrow[c * 4];
#pragma unroll
        for (int u = 0; u < 4; u++) {
            const int j = c * 4 + u;
            const float4* wj = (const float4*)&sDW3T[j * 16];
            float4 w0 = wj[0], w1 = wj[1], w2 = wj[2], w3 = wj[3];
            float y = sDB3[j];
            y = fmaf(d2[0],  w0.x, y);
            y = fmaf(d2[1],  w0.y, y);
            y = fmaf(d2[2],  w0.z, y);
            y = fmaf(d2[3],  w0.w, y);
            y = fmaf(d2[4],  w1.x, y);
            y = fmaf(d2[5],  w1.y, y);
            y = fmaf(d2[6],  w1.z, y);
            y = fmaf(d2[7],  w1.w, y);
            y = fmaf(d2[8],  w2.x, y);
            y = fmaf(d2[9],  w2.y, y);
            y = fmaf(d2[10], w2.z, y);
            y = fmaf(d2[11], w2.w, y);
            y = fmaf(d2[12], w3.x, y);
            y = fmaf(d2[13], w3.y, y);
            y = fmaf(d2[14], w3.z, y);
            y = fmaf(d2[15], w3.w, y);
            float xsv = (u == 0) ? xv.x : (u == 1) ? xv.y : (u == 2) ? xv.z : xv.w;
            dotv = fmaf(xsv, y, dotv);
            n2   = fmaf(y, y, n2);
            float d = xsv - y;
            e2   = fmaf(d, d, e2);
        }
    }

    // ---------------- distances, estimator, softmax ----------------
    float prod = sqrtf(n1) * sqrtf(n2);
    float cd = __fdividef(dotv, prod);
    float ed = sqrtf(e2);

    float eh[8];
#pragma unroll
    for (int j = 0; j < 8; j++) {
        float t = sTB1[j];
        t = fmaf(z1v, sTW1[j],      t);
        t = fmaf(cd,  sTW1[8 + j],  t);
        t = fmaf(ed,  sTW1[16 + j], t);
        eh[j] = tanh_f(t);
    }
    float lg[4];
#pragma unroll
    for (int k = 0; k < 4; k++) {
        float t = sTB2[k];
#pragma unroll
        for (int i = 0; i < 8; i++) t = fmaf(eh[i], sTW2[i * 4 + k], t);
        lg[k] = t;
    }
    float m = fmaxf(fmaxf(lg[0], lg[1]), fmaxf(lg[2], lg[3]));
    float es[4], ssum = 0.f;
#pragma unroll
    for (int k = 0; k < 4; k++) { es[k] = __expf(lg[k] - m); ssum += es[k]; }
    float inv = __fdividef(validf, ssum);          // folds validity into gamma
    float gam[4];
#pragma unroll
    for (int k = 0; k < 4; k++) gam[k] = es[k] * inv;

    if (row < n) {                                 // coalesced stores
        g_z[row]            = z1v;
        g_z[MAXN + row]     = cd;
        g_z[2 * MAXN + row] = ed;
    }

    // ---------------- moments: warp reduce -> block reduce -> atomics ----------------
    float vals[41];
    {
        float p00 = z1v * z1v, p01 = z1v * cd, p02 = z1v * ed;
        float p11 = cd * cd,   p12 = cd * ed,  p22 = ed * ed;
        vals[40] = e2 * validf;
#pragma unroll
        for (int k = 0; k < 4; k++) {
            float gk = gam[k];
            vals[k]              = gk;
            vals[4 + k * 3 + 0]  = gk * z1v;
            vals[4 + k * 3 + 1]  = gk * cd;
            vals[4 + k * 3 + 2]  = gk * ed;
            vals[16 + k * 6 + 0] = gk * p00;
            vals[16 + k * 6 + 1] = gk * p01;
            vals[16 + k * 6 + 2] = gk * p02;
            vals[16 + k * 6 + 3] = gk * p11;
            vals[16 + k * 6 + 4] = gk * p12;
            vals[16 + k * 6 + 5] = gk * p22;
        }
    }
    const int wid = tid >> 5, lane = tid & 31;
#pragma unroll
    for (int q = 0; q < 41; q++) {
        float r = wsum(vals[q]);
        if (lane == 0) sRed[wid][q] = r;
    }
    __syncthreads();
    if (tid < 41) {
        float r = sRed[0][tid] + sRed[1][tid] + sRed[2][tid] + sRed[3][tid];
        atomicAdd(&g_acc[tid], (double)r);
    }
}

// energy kernel: each block re-derives GMM params from g_acc (tiny), then per-sample energy
__global__ void __launch_bounds__(256) energy_kernel(float* __restrict__ out, int n) {
    __shared__ float s_mu[4][3], s_si[4][6], s_c[4];
    __shared__ float sE[8];
    const int tid = threadIdx.x;

    if (tid == 0) {
        const double TWO_PI = 6.283185307179586;
        for (int k = 0; k < 4; k++) {
            double gs = g_acc[k];
            double m0 = g_acc[4 + k * 3 + 0] / gs;
            double m1 = g_acc[4 + k * 3 + 1] / gs;
            double m2 = g_acc[4 + k * 3 + 2] / gs;
            double a = g_acc[16 + k * 6 + 0] / gs - m0 * m0;
            double b = g_acc[16 + k * 6 + 1] / gs - m0 * m1;
            double c = g_acc[16 + k * 6 + 2] / gs - m0 * m2;
            double d = g_acc[16 + k * 6 + 3] / gs - m1 * m1;
            double e = g_acc[16 + k * 6 + 4] / gs - m1 * m2;
            double f = g_acc[16 + k * 6 + 5] / gs - m2 * m2;
            double det = a * (d * f - e * e) - b * (b * f - c * e) + c * (b * e - c * d);
            double id = 1.0 / det;
            s_si[k][0] = (float)((d * f - e * e) * id);
            s_si[k][1] = (float)((c * e - b * f) * id);
            s_si[k][2] = (float)((b * e - c * d) * id);
            s_si[k][3] = (float)((a * f - c * c) * id);
            s_si[k][4] = (float)((b * c - a * e) * id);
            s_si[k][5] = (float)((a * d - b * b) * id);
            s_mu[k][0] = (float)m0; s_mu[k][1] = (float)m1; s_mu[k][2] = (float)m2;
            double phi = gs / (double)n;
            // item3 - logphi
            s_c[k] = (float)(0.5 * log(TWO_PI * TWO_PI * TWO_PI * det) - log(phi));
        }
    }
    __syncthreads();

    int i = blockIdx.x * blockDim.x + tid;
    bool v = i < n;
    int ii = v ? i : 0;
    float z0 = g_z[ii], zc = g_z[MAXN + ii], ze = g_z[2 * MAXN + ii];
    float en = 0.f;
#pragma unroll
    for (int k = 0; k < 4; k++) {
        float a = z0 - s_mu[k][0];
        float b = zc - s_mu[k][1];
        float c = ze - s_mu[k][2];
        float q = s_si[k][0] * a * a + s_si[k][3] * b * b + s_si[k][5] * c * c
                + 2.f * (s_si[k][1] * a * b + s_si[k][2] * a * c + s_si[k][4] * b * c);
        en += s_c[k] + 0.5f * q;
    }
    if (v) out[i] = en;

    float r = wsum(v ? en : 0.f);
    const int wid = tid >> 5, lane = tid & 31;
    if (lane == 0) sE[wid] = r;
    __syncthreads();
    if (tid == 0) {
        float t = 0.f;
#pragma unroll
        for (int w = 0; w < 8; w++) t += sE[w];
        atomicAdd(&g_acc[41], (double)t);
    }
}

__global__ void loss_kernel(float* __restrict__ out, int n, int has_loss) {
    if (threadIdx.x == 0 && has_loss) {
        double loss3 = 0.0;
        for (int k = 0; k < 4; k++) {
            double gs = g_acc[k];
            double m0 = g_acc[4 + k * 3 + 0] / gs;
            double m1 = g_acc[4 + k * 3 + 1] / gs;
            double m2 = g_acc[4 + k * 3 + 2] / gs;
            double a = g_acc[16 + k * 6 + 0] / gs - m0 * m0;
            double d = g_acc[16 + k * 6 + 3] / gs - m1 * m1;
            double f = g_acc[16 + k * 6 + 5] / gs - m2 * m2;
            loss3 += 1.0 / a + 1.0 / d + 1.0 / f;
        }
        double loss = g_acc[40] / (double)n + 0.01 * (g_acc[41] / (double)n) + 1e-4 * loss3;
        out[n] = (float)loss;
    }
}

extern "C" void kernel_launch(void* const* d_in, const int* in_sizes, int n_in,
                              void* d_out, int out_size) {
    const float* x1  = (const float*)d_in[0];
    const float* ew1 = (const float*)d_in[1];
    const float* eb1 = (const float*)d_in[2];
    const float* ew2 = (const float*)d_in[3];
    const float* eb2 = (const float*)d_in[4];
    const float* ew3 = (const float*)d_in[5];
    const float* eb3 = (const float*)d_in[6];
    const float* dw1 = (const float*)d_in[7];
    const float* db1 = (const float*)d_in[8];
    const float* dw2 = (const float*)d_in[9];
    const float* db2 = (const float*)d_in[10];
    const float* dw3 = (const float*)d_in[11];
    const float* db3 = (const float*)d_in[12];
    const float* tw1 = (const float*)d_in[13];
    const float* tb1 = (const float*)d_in[14];
    const float* tw2 = (const float*)d_in[15];
    const float* tb2 = (const float*)d_in[16];

    int n = in_sizes[0] / 128;
    if (n > MAXN) n = MAXN;
    float* out = (float*)d_out;

    cudaFuncSetAttribute(fwd_kernel, cudaFuncAttributeMaxDynamicSharedMemorySize, XS_BYTES);

    zero_kernel<<<1, 64>>>();
    int blocks = (n + TPB - 1) / TPB;
    fwd_kernel<<<blocks, TPB, XS_BYTES>>>(x1, ew1, eb1, ew2, eb2, ew3, eb3,
                                          dw1, db1, dw2, db2, dw3, db3,
                                          tw1, tb1, tw2, tb2, n);
    energy_kernel<<<(n + 255) / 256, 256>>>(out, n);
    loss_kernel<<<1, 32>>>(out, n, out_size > n ? 1 : 0);
}

// round 7
// speedup vs baseline: 1.1621x; 1.1621x over previous
#include <cuda_runtime.h>
#include <math.h>

#define MAXN 400000
#define TPB  128

// Accumulators: [0..3]=S0(k)  [4..15]=S1(k*3+d)  [16..39]=S2(k*6+m)  [40]=loss1  [41]=esum
__device__ double g_acc[42];
__device__ float  g_z[3 * MAXN];          // planar: z1 | cos | euc
__device__ float  g_G[256];               // W3 W3^T  (16x16)
__device__ float  g_w3b[16];              // W3 b
__device__ float  g_bb[1];                // b.b

__device__ __forceinline__ float tanh_f(float x) {
    float y = fminf(fmaxf(x, -8.f), 8.f);
    float e = __expf(2.f * y);
    return __fdividef(e - 1.f, e + 1.f);
}

__device__ __forceinline__ float wsum(float v) {
#pragma unroll
    for (int o = 16; o; o >>= 1) v += __shfl_down_sync(0xffffffffu, v, o);
    return v;
}

__global__ void zero_kernel() {
    int t = threadIdx.x;
    if (t < 42) g_acc[t] = 0.0;
}

// Precompute G = W3 W3^T, w3b = W3 b, bb = b.b   (dw3: [16][128] row-major)
__global__ void prep_kernel(const float* __restrict__ dw3, const float* __restrict__ db3) {
    int t = threadIdx.x;              // 256 threads
    int i = t >> 4, j = t & 15;
    float s = 0.f;
#pragma unroll 4
    for (int k = 0; k < 128; k++) s = fmaf(dw3[i * 128 + k], dw3[j * 128 + k], s);
    g_G[t] = s;
    if (t < 16) {
        float w = 0.f;
#pragma unroll 4
        for (int k = 0; k < 128; k++) w = fmaf(dw3[t * 128 + k], db3[k], w);
        g_w3b[t] = w;
    }
    if (t == 0) {
        float b = 0.f;
#pragma unroll 4
        for (int k = 0; k < 128; k++) b = fmaf(db3[k], db3[k], b);
        g_bb[0] = b;
    }
}

__global__ void __launch_bounds__(TPB) fwd_kernel(
    const float* __restrict__ x1,
    const float* __restrict__ ew1, const float* __restrict__ eb1,
    const float* __restrict__ ew2, const float* __restrict__ eb2,
    const float* __restrict__ ew3, const float* __restrict__ eb3,
    const float* __restrict__ dw1, const float* __restrict__ db1,
    const float* __restrict__ dw2, const float* __restrict__ db2,
    const float* __restrict__ dw3, const float* __restrict__ db3,
    const float* __restrict__ tw1, const float* __restrict__ tb1,
    const float* __restrict__ tw2, const float* __restrict__ tb2,
    int n)
{
    // combined weights: sWC[col][0..15]=enc_w1 row col ; sWC[col][16..31]=dw3[:,col]
    __shared__ __align__(16) float sWC[128 * 32];
    __shared__ __align__(16) float sG[256];
    __shared__ __align__(16) float sW3B[16];
    __shared__ __align__(16) float sB1[16];
    __shared__ __align__(16) float sW2[128];
    __shared__ __align__(16) float sB2[8];
    __shared__ __align__(16) float sW3[8];
    __shared__ __align__(16) float sDW1[8];
    __shared__ __align__(16) float sDB1[8];
    __shared__ __align__(16) float sDW2[128];
    __shared__ __align__(16) float sDB2[16];
    __shared__ __align__(16) float sDB3[128];
    __shared__ __align__(16) float sTW1[24];
    __shared__ __align__(16) float sTB1[8];
    __shared__ __align__(16) float sTW2[32];
    __shared__ __align__(16) float sTB2[4];
    __shared__ float sB3, sBB;
    __shared__ float sRed[4][41];

    const int tid = threadIdx.x;

    // -------- stage weights --------
    for (int i = tid; i < 2048; i += TPB) { int c = i >> 4, o = i & 15; sWC[c * 32 + o] = ew1[i]; }
    for (int i = tid; i < 2048; i += TPB) { int r = i >> 7, c = i & 127; sWC[c * 32 + 16 + r] = dw3[i]; }
    for (int i = tid; i < 256; i += TPB) sG[i] = g_G[i];
    for (int i = tid; i < 128; i += TPB) { sW2[i] = ew2[i]; sDW2[i] = dw2[i]; sDB3[i] = db3[i]; }
    if (tid < 16) { sB1[tid] = eb1[tid]; sDB2[tid] = db2[tid]; sW3B[tid] = g_w3b[tid]; }
    if (tid < 8)  { sB2[tid] = eb2[tid]; sW3[tid] = ew3[tid]; sDW1[tid] = dw1[tid]; sDB1[tid] = db1[tid]; sTB1[tid] = tb1[tid]; }
    if (tid < 24) sTW1[tid] = tw1[tid];
    if (tid < 32) sTW2[tid] = tw2[tid];
    if (tid < 4)  sTB2[tid] = tb2[tid];
    if (tid == 0) { sB3 = eb3[0]; sBB = g_bb[0]; }
    __syncthreads();

    const int row = blockIdx.x * TPB + tid;
    const float validf = (row < n) ? 1.f : 0.f;
    const int rr = (row < n) ? row : 0;
    const float4* xp = (const float4*)(x1 + (size_t)rr * 128);

    // ---------------- single pass over x: enc1 (128->16), u=W3 x (128->16), n1, bx ----------------
    float acc[32];
#pragma unroll
    for (int j = 0; j < 16; j++) acc[j] = sB1[j];
#pragma unroll
    for (int j = 16; j < 32; j++) acc[j] = 0.f;
    float n1 = 0.f, bx = 0.f;

#pragma unroll 2
    for (int c = 0; c < 32; c++) {
        float4 v = xp[c];
        n1 = fmaf(v.x, v.x, fmaf(v.y, v.y, fmaf(v.z, v.z, fmaf(v.w, v.w, n1))));
#pragma unroll
        for (int r = 0; r < 4; r++) {
            const int col = c * 4 + r;
            float xv = (r == 0) ? v.x : (r == 1) ? v.y : (r == 2) ? v.z : v.w;
            bx = fmaf(xv, sDB3[col], bx);
            const float4* w = (const float4*)&sWC[col * 32];
#pragma unroll
            for (int q = 0; q < 8; q++) {
                float4 wq = w[q];
                acc[q * 4 + 0] = fmaf(xv, wq.x, acc[q * 4 + 0]);
                acc[q * 4 + 1] = fmaf(xv, wq.y, acc[q * 4 + 1]);
                acc[q * 4 + 2] = fmaf(xv, wq.z, acc[q * 4 + 2]);
                acc[q * 4 + 3] = fmaf(xv, wq.w, acc[q * 4 + 3]);
            }
        }
    }

    float h1[16];
#pragma unroll
    for (int j = 0; j < 16; j++) h1[j] = tanh_f(acc[j]);

    // ---------------- encoder layer 2 (16->8) ----------------
    float h2[8];
#pragma unroll
    for (int j = 0; j < 8; j++) {
        float t = sB2[j];
#pragma unroll
        for (int i = 0; i < 16; i++) t = fmaf(h1[i], sW2[i * 8 + j], t);
        h2[j] = tanh_f(t);
    }

    // ---------------- encoder layer 3 (8->1) ----------------
    float z1v;
    {
        float t = sB3;
#pragma unroll
        for (int i = 0; i < 8; i++) t = fmaf(h2[i], sW3[i], t);
        z1v = tanh_f(t);
    }

    // ---------------- decoder layer 1 (1->8) ----------------
    float d1[8];
#pragma unroll
    for (int j = 0; j < 8; j++) d1[j] = tanh_f(fmaf(z1v, sDW1[j], sDB1[j]));

    // ---------------- decoder layer 2 (8->16) ----------------
    float d2[16];
#pragma unroll
    for (int j = 0; j < 16; j++) {
        float t = sDB2[j];
#pragma unroll
        for (int i = 0; i < 8; i++) t = fmaf(d1[i], sDW2[i * 16 + j], t);
        d2[j] = tanh_f(t);
    }

    // ---------------- distances via precomputed Gram ----------------
    // dot(x,x2) = d2.u + b.x ;  ||x2||^2 = d2'G d2 + 2 d2.w3b + bb ;  e2 = n1 - 2dot + n2
    float dotv = bx;
#pragma unroll
    for (int i = 0; i < 16; i++) dotv = fmaf(d2[i], acc[16 + i], dotv);

    float n2 = sBB;
#pragma unroll
    for (int i = 0; i < 16; i++) {
        float gi = 2.f * sW3B[i];
#pragma unroll
        for (int j = 0; j < 16; j++) gi = fmaf(sG[i * 16 + j], d2[j], gi);
        n2 = fmaf(d2[i], gi, n2);
    }
    float e2 = fmaxf(n1 - 2.f * dotv + n2, 0.f);

    float prod = sqrtf(n1) * sqrtf(n2);
    float cd = __fdividef(dotv, prod);
    float ed = sqrtf(e2);

    // ---------------- estimator + softmax ----------------
    float eh[8];
#pragma unroll
    for (int j = 0; j < 8; j++) {
        float t = sTB1[j];
        t = fmaf(z1v, sTW1[j],      t);
        t = fmaf(cd,  sTW1[8 + j],  t);
        t = fmaf(ed,  sTW1[16 + j], t);
        eh[j] = tanh_f(t);
    }
    float lg[4];
#pragma unroll
    for (int k = 0; k < 4; k++) {
        float t = sTB2[k];
#pragma unroll
        for (int i = 0; i < 8; i++) t = fmaf(eh[i], sTW2[i * 4 + k], t);
        lg[k] = t;
    }
    float m = fmaxf(fmaxf(lg[0], lg[1]), fmaxf(lg[2], lg[3]));
    float es[4], ssum = 0.f;
#pragma unroll
    for (int k = 0; k < 4; k++) { es[k] = __expf(lg[k] - m); ssum += es[k]; }
    float inv = __fdividef(validf, ssum);          // folds validity into gamma
    float gam[4];
#pragma unroll
    for (int k = 0; k < 4; k++) gam[k] = es[k] * inv;

    if (row < n) {                                 // coalesced stores
        g_z[row]            = z1v;
        g_z[MAXN + row]     = cd;
        g_z[2 * MAXN + row] = ed;
    }

    // ---------------- moments: warp reduce -> block reduce -> atomics ----------------
    float vals[41];
    {
        float p00 = z1v * z1v, p01 = z1v * cd, p02 = z1v * ed;
        float p11 = cd * cd,   p12 = cd * ed,  p22 = ed * ed;
        vals[40] = e2 * validf;
#pragma unroll
        for (int k = 0; k < 4; k++) {
            float gk = gam[k];
            vals[k]              = gk;
            vals[4 + k * 3 + 0]  = gk * z1v;
            vals[4 + k * 3 + 1]  = gk * cd;
            vals[4 + k * 3 + 2]  = gk * ed;
            vals[16 + k * 6 + 0] = gk * p00;
            vals[16 + k * 6 + 1] = gk * p01;
            vals[16 + k * 6 + 2] = gk * p02;
            vals[16 + k * 6 + 3] = gk * p11;
            vals[16 + k * 6 + 4] = gk * p12;
            vals[16 + k * 6 + 5] = gk * p22;
        }
    }
    const int wid = tid >> 5, lane = tid & 31;
#pragma unroll
    for (int q = 0; q < 41; q++) {
        float r = wsum(vals[q]);
        if (lane == 0) sRed[wid][q] = r;
    }
    __syncthreads();
    if (tid < 41) {
        float r = sRed[0][tid] + sRed[1][tid] + sRed[2][tid] + sRed[3][tid];
        atomicAdd(&g_acc[tid], (double)r);
    }
}

// energy kernel: each block re-derives GMM params from g_acc (tiny), then per-sample energy
__global__ void __launch_bounds__(256) energy_kernel(float* __restrict__ out, int n) {
    __shared__ float s_mu[4][3], s_si[4][6], s_c[4];
    __shared__ float sE[8];
    const int tid = threadIdx.x;

    if (tid == 0) {
        const double TWO_PI = 6.283185307179586;
        for (int k = 0; k < 4; k++) {
            double gs = g_acc[k];
            double m0 = g_acc[4 + k * 3 + 0] / gs;
            double m1 = g_acc[4 + k * 3 + 1] / gs;
            double m2 = g_acc[4 + k * 3 + 2] / gs;
            double a = g_acc[16 + k * 6 + 0] / gs - m0 * m0;
            double b = g_acc[16 + k * 6 + 1] / gs - m0 * m1;
            double c = g_acc[16 + k * 6 + 2] / gs - m0 * m2;
            double d = g_acc[16 + k * 6 + 3] / gs - m1 * m1;
            double e = g_acc[16 + k * 6 + 4] / gs - m1 * m2;
            double f = g_acc[16 + k * 6 + 5] / gs - m2 * m2;
            double det = a * (d * f - e * e) - b * (b * f - c * e) + c * (b * e - c * d);
            double id = 1.0 / det;
            s_si[k][0] = (float)((d * f - e * e) * id);
            s_si[k][1] = (float)((c * e - b * f) * id);
            s_si[k][2] = (float)((b * e - c * d) * id);
            s_si[k][3] = (float)((a * f - c * c) * id);
            s_si[k][4] = (float)((b * c - a * e) * id);
            s_si[k][5] = (float)((a * d - b * b) * id);
            s_mu[k][0] = (float)m0; s_mu[k][1] = (float)m1; s_mu[k][2] = (float)m2;
            double phi = gs / (double)n;
            s_c[k] = (float)(0.5 * log(TWO_PI * TWO_PI * TWO_PI * det) - log(phi));
        }
    }
    __syncthreads();

    int i = blockIdx.x * blockDim.x + tid;
    bool v = i < n;
    int ii = v ? i : 0;
    float z0 = g_z[ii], zc = g_z[MAXN + ii], ze = g_z[2 * MAXN + ii];
    float en = 0.f;
#pragma unroll
    for (int k = 0; k < 4; k++) {
        float a = z0 - s_mu[k][0];
        float b = zc - s_mu[k][1];
        float c = ze - s_mu[k][2];
        float q = s_si[k][0] * a * a + s_si[k][3] * b * b + s_si[k][5] * c * c
                + 2.f * (s_si[k][1] * a * b + s_si[k][2] * a * c + s_si[k][4] * b * c);
        en += s_c[k] + 0.5f * q;
    }
    if (v) out[i] = en;

    float r = wsum(v ? en : 0.f);
    const int wid = tid >> 5, lane = tid & 31;
    if (lane == 0) sE[wid] = r;
    __syncthreads();
    if (tid == 0) {
        float t = 0.f;
#pragma unroll
        for (int w = 0; w < 8; w++) t += sE[w];
        atomicAdd(&g_acc[41], (double)t);
    }
}

__global__ void loss_kernel(float* __restrict__ out, int n, int has_loss) {
    if (threadIdx.x == 0 && has_loss) {
        double loss3 = 0.0;
        for (int k = 0; k < 4; k++) {
            double gs = g_acc[k];
            double m0 = g_acc[4 + k * 3 + 0] / gs;
            double m1 = g_acc[4 + k * 3 + 1] / gs;
            double m2 = g_acc[4 + k * 3 + 2] / gs;
            double a = g_acc[16 + k * 6 + 0] / gs - m0 * m0;
            double d = g_acc[16 + k * 6 + 3] / gs - m1 * m1;
            double f = g_acc[16 + k * 6 + 5] / gs - m2 * m2;
            loss3 += 1.0 / a + 1.0 / d + 1.0 / f;
        }
        double loss = g_acc[40] / (double)n + 0.01 * (g_acc[41] / (double)n) + 1e-4 * loss3;
        out[n] = (float)loss;
    }
}

extern "C" void kernel_launch(void* const* d_in, const int* in_sizes, int n_in,
                              void* d_out, int out_size) {
    const float* x1  = (const float*)d_in[0];
    const float* ew1 = (const float*)d_in[1];
    const float* eb1 = (const float*)d_in[2];
    const float* ew2 = (const float*)d_in[3];
    const float* eb2 = (const float*)d_in[4];
    const float* ew3 = (const float*)d_in[5];
    const float* eb3 = (const float*)d_in[6];
    const float* dw1 = (const float*)d_in[7];
    const float* db1 = (const float*)d_in[8];
    const float* dw2 = (const float*)d_in[9];
    const float* db2 = (const float*)d_in[10];
    const float* dw3 = (const float*)d_in[11];
    const float* db3 = (const float*)d_in[12];
    const float* tw1 = (const float*)d_in[13];
    const float* tb1 = (const float*)d_in[14];
    const float* tw2 = (const float*)d_in[15];
    const float* tb2 = (const float*)d_in[16];

    int n = in_sizes[0] / 128;
    if (n > MAXN) n = MAXN;
    float* out = (float*)d_out;

    zero_kernel<<<1, 64>>>();
    prep_kernel<<<1, 256>>>(dw3, db3);
    int blocks = (n + TPB - 1) / TPB;
    fwd_kernel<<<blocks, TPB>>>(x1, ew1, eb1, ew2, eb2, ew3, eb3,
                                dw1, db1, dw2, db2, dw3, db3,
                                tw1, tb1, tw2, tb2, n);
    energy_kernel<<<(n + 255) / 256, 256>>>(out, n);
    loss_kernel<<<1, 32>>>(out, n, out_size > n ? 1 : 0);
}

// round 8
// speedup vs baseline: 1.6239x; 1.3974x over previous
#include <cuda_runtime.h>
#include <math.h>

#define MAXN 400000
#define TPB  128

// Accumulators: [0..3]=S0(k)  [4..15]=S1(k*3+d)  [16..39]=S2(k*6+m)  [40]=loss1  [41]=esum
__device__ double g_acc[42];
__device__ float  g_z[3 * MAXN];          // planar: z1 | cos | euc
__device__ float  g_G[256];               // W3 W3^T  (16x16)
__device__ float  g_w3b[16];              // W3 b
__device__ float  g_bb[1];                // b.b
// GMM params derived once by finalize_kernel
__device__ float  g_mu[12];               // [k][3]
__device__ float  g_si[24];               // [k][6] packed sym inverse
__device__ float  g_c[4];                 // item3 - logphi per k
__device__ double g_loss3;

__device__ __forceinline__ float tanh_f(float x) {
    float y = fminf(fmaxf(x, -8.f), 8.f);
    float e = __expf(2.f * y);
    return __fdividef(e - 1.f, e + 1.f);
}

__device__ __forceinline__ float wsum(float v) {
#pragma unroll
    for (int o = 16; o; o >>= 1) v += __shfl_down_sync(0xffffffffu, v, o);
    return v;
}

// Precompute G = W3 W3^T, w3b = W3 b, bb = b.b   (dw3: [16][128] row-major)
// Also zeroes the accumulators (folded zero_kernel).
__global__ void prep_kernel(const float* __restrict__ dw3, const float* __restrict__ db3) {
    int t = threadIdx.x;              // 256 threads
    if (t < 42) g_acc[t] = 0.0;
    int i = t >> 4, j = t & 15;
    float s = 0.f;
#pragma unroll 4
    for (int k = 0; k < 128; k++) s = fmaf(dw3[i * 128 + k], dw3[j * 128 + k], s);
    g_G[t] = s;
    if (t < 16) {
        float w = 0.f;
#pragma unroll 4
        for (int k = 0; k < 128; k++) w = fmaf(dw3[t * 128 + k], db3[k], w);
        g_w3b[t] = w;
    }
    if (t == 0) {
        float b = 0.f;
#pragma unroll 4
        for (int k = 0; k < 128; k++) b = fmaf(db3[k], db3[k], b);
        g_bb[0] = b;
    }
}

__global__ void __launch_bounds__(TPB) fwd_kernel(
    const float* __restrict__ x1,
    const float* __restrict__ ew1, const float* __restrict__ eb1,
    const float* __restrict__ ew2, const float* __restrict__ eb2,
    const float* __restrict__ ew3, const float* __restrict__ eb3,
    const float* __restrict__ dw1, const float* __restrict__ db1,
    const float* __restrict__ dw2, const float* __restrict__ db2,
    const float* __restrict__ dw3, const float* __restrict__ db3,
    const float* __restrict__ tw1, const float* __restrict__ tb1,
    const float* __restrict__ tw2, const float* __restrict__ tb2,
    int n)
{
    // combined weights: sWC[col][0..15]=enc_w1 row col ; sWC[col][16..31]=dw3[:,col]
    __shared__ __align__(16) float sWC[128 * 32];
    __shared__ __align__(16) float sG[256];
    __shared__ __align__(16) float sW3B[16];
    __shared__ __align__(16) float sB1[16];
    __shared__ __align__(16) float sW2[128];
    __shared__ __align__(16) float sB2[8];
    __shared__ __align__(16) float sW3[8];
    __shared__ __align__(16) float sDW1[8];
    __shared__ __align__(16) float sDB1[8];
    __shared__ __align__(16) float sDW2[128];
    __shared__ __align__(16) float sDB2[16];
    __shared__ __align__(16) float sDB3[128];
    __shared__ __align__(16) float sTW1[24];
    __shared__ __align__(16) float sTB1[8];
    __shared__ __align__(16) float sTW2[32];
    __shared__ __align__(16) float sTB2[4];
    __shared__ float sB3, sBB;
    __shared__ float sRed[4][41];

    const int tid = threadIdx.x;

    // -------- stage weights --------
    for (int i = tid; i < 2048; i += TPB) { int c = i >> 4, o = i & 15; sWC[c * 32 + o] = ew1[i]; }
    for (int i = tid; i < 2048; i += TPB) { int r = i >> 7, c = i & 127; sWC[c * 32 + 16 + r] = dw3[i]; }
    for (int i = tid; i < 256; i += TPB) sG[i] = g_G[i];
    for (int i = tid; i < 128; i += TPB) { sW2[i] = ew2[i]; sDW2[i] = dw2[i]; sDB3[i] = db3[i]; }
    if (tid < 16) { sB1[tid] = eb1[tid]; sDB2[tid] = db2[tid]; sW3B[tid] = g_w3b[tid]; }
    if (tid < 8)  { sB2[tid] = eb2[tid]; sW3[tid] = ew3[tid]; sDW1[tid] = dw1[tid]; sDB1[tid] = db1[tid]; sTB1[tid] = tb1[tid]; }
    if (tid < 24) sTW1[tid] = tw1[tid];
    if (tid < 32) sTW2[tid] = tw2[tid];
    if (tid < 4)  sTB2[tid] = tb2[tid];
    if (tid == 0) { sB3 = eb3[0]; sBB = g_bb[0]; }
    __syncthreads();

    const int row = blockIdx.x * TPB + tid;
    const float validf = (row < n) ? 1.f : 0.f;
    const int rr = (row < n) ? row : 0;
    const float4* xp = (const float4*)(x1 + (size_t)rr * 128);

    // ---------------- single pass over x: enc1 (128->16), u=W3 x (128->16), n1, bx ----------------
    float acc[32];
#pragma unroll
    for (int j = 0; j < 16; j++) acc[j] = sB1[j];
#pragma unroll
    for (int j = 16; j < 32; j++) acc[j] = 0.f;
    float n1 = 0.f, bx = 0.f;

#pragma unroll 2
    for (int c = 0; c < 32; c++) {
        float4 v = xp[c];
        n1 = fmaf(v.x, v.x, fmaf(v.y, v.y, fmaf(v.z, v.z, fmaf(v.w, v.w, n1))));
#pragma unroll
        for (int r = 0; r < 4; r++) {
            const int col = c * 4 + r;
            float xv = (r == 0) ? v.x : (r == 1) ? v.y : (r == 2) ? v.z : v.w;
            bx = fmaf(xv, sDB3[col], bx);
            const float4* w = (const float4*)&sWC[col * 32];
#pragma unroll
            for (int q = 0; q < 8; q++) {
                float4 wq = w[q];
                acc[q * 4 + 0] = fmaf(xv, wq.x, acc[q * 4 + 0]);
                acc[q * 4 + 1] = fmaf(xv, wq.y, acc[q * 4 + 1]);
                acc[q * 4 + 2] = fmaf(xv, wq.z, acc[q * 4 + 2]);
                acc[q * 4 + 3] = fmaf(xv, wq.w, acc[q * 4 + 3]);
            }
        }
    }

    float h1[16];
#pragma unroll
    for (int j = 0; j < 16; j++) h1[j] = tanh_f(acc[j]);

    // ---------------- encoder layer 2 (16->8) ----------------
    float h2[8];
#pragma unroll
    for (int j = 0; j < 8; j++) {
        float t = sB2[j];
#pragma unroll
        for (int i = 0; i < 16; i++) t = fmaf(h1[i], sW2[i * 8 + j], t);
        h2[j] = tanh_f(t);
    }

    // ---------------- encoder layer 3 (8->1) ----------------
    float z1v;
    {
        float t = sB3;
#pragma unroll
        for (int i = 0; i < 8; i++) t = fmaf(h2[i], sW3[i], t);
        z1v = tanh_f(t);
    }

    // ---------------- decoder layer 1 (1->8) ----------------
    float d1[8];
#pragma unroll
    for (int j = 0; j < 8; j++) d1[j] = tanh_f(fmaf(z1v, sDW1[j], sDB1[j]));

    // ---------------- decoder layer 2 (8->16) ----------------
    float d2[16];
#pragma unroll
    for (int j = 0; j < 16; j++) {
        float t = sDB2[j];
#pragma unroll
        for (int i = 0; i < 8; i++) t = fmaf(d1[i], sDW2[i * 16 + j], t);
        d2[j] = tanh_f(t);
    }

    // ---------------- distances via precomputed Gram ----------------
    // dot(x,x2) = d2.u + b.x ;  ||x2||^2 = d2'G d2 + 2 d2.w3b + bb ;  e2 = n1 - 2dot + n2
    float dotv = bx;
#pragma unroll
    for (int i = 0; i < 16; i++) dotv = fmaf(d2[i], acc[16 + i], dotv);

    float n2 = sBB;
#pragma unroll
    for (int i = 0; i < 16; i++) {
        float gi = 2.f * sW3B[i];
#pragma unroll
        for (int j = 0; j < 16; j++) gi = fmaf(sG[i * 16 + j], d2[j], gi);
        n2 = fmaf(d2[i], gi, n2);
    }
    float e2 = fmaxf(n1 - 2.f * dotv + n2, 0.f);

    float prod = sqrtf(n1) * sqrtf(n2);
    float cd = __fdividef(dotv, prod);
    float ed = sqrtf(e2);

    // ---------------- estimator + softmax ----------------
    float eh[8];
#pragma unroll
    for (int j = 0; j < 8; j++) {
        float t = sTB1[j];
        t = fmaf(z1v, sTW1[j],      t);
        t = fmaf(cd,  sTW1[8 + j],  t);
        t = fmaf(ed,  sTW1[16 + j], t);
        eh[j] = tanh_f(t);
    }
    float lg[4];
#pragma unroll
    for (int k = 0; k < 4; k++) {
        float t = sTB2[k];
#pragma unroll
        for (int i = 0; i < 8; i++) t = fmaf(eh[i], sTW2[i * 4 + k], t);
        lg[k] = t;
    }
    float m = fmaxf(fmaxf(lg[0], lg[1]), fmaxf(lg[2], lg[3]));
    float es[4], ssum = 0.f;
#pragma unroll
    for (int k = 0; k < 4; k++) { es[k] = __expf(lg[k] - m); ssum += es[k]; }
    float inv = __fdividef(validf, ssum);          // folds validity into gamma
    float gam[4];
#pragma unroll
    for (int k = 0; k < 4; k++) gam[k] = es[k] * inv;

    if (row < n) {                                 // coalesced stores
        g_z[row]            = z1v;
        g_z[MAXN + row]     = cd;
        g_z[2 * MAXN + row] = ed;
    }

    // ---------------- moments: warp reduce -> block reduce -> atomics ----------------
    float vals[41];
    {
        float p00 = z1v * z1v, p01 = z1v * cd, p02 = z1v * ed;
        float p11 = cd * cd,   p12 = cd * ed,  p22 = ed * ed;
        vals[40] = e2 * validf;
#pragma unroll
        for (int k = 0; k < 4; k++) {
            float gk = gam[k];
            vals[k]              = gk;
            vals[4 + k * 3 + 0]  = gk * z1v;
            vals[4 + k * 3 + 1]  = gk * cd;
            vals[4 + k * 3 + 2]  = gk * ed;
            vals[16 + k * 6 + 0] = gk * p00;
            vals[16 + k * 6 + 1] = gk * p01;
            vals[16 + k * 6 + 2] = gk * p02;
            vals[16 + k * 6 + 3] = gk * p11;
            vals[16 + k * 6 + 4] = gk * p12;
            vals[16 + k * 6 + 5] = gk * p22;
        }
    }
    const int wid = tid >> 5, lane = tid & 31;
#pragma unroll
    for (int q = 0; q < 41; q++) {
        float r = wsum(vals[q]);
        if (lane == 0) sRed[wid][q] = r;
    }
    __syncthreads();
    if (tid < 41) {
        float r = sRed[0][tid] + sRed[1][tid] + sRed[2][tid] + sRed[3][tid];
        atomicAdd(&g_acc[tid], (double)r);
    }
}

// Derive GMM parameters ONCE (k-parallel, 4 threads active)
__global__ void finalize_kernel(int n) {
    int k = threadIdx.x;
    if (k < 4) {
        const double TWO_PI = 6.283185307179586;
        double gs = g_acc[k];
        double m0 = g_acc[4 + k * 3 + 0] / gs;
        double m1 = g_acc[4 + k * 3 + 1] / gs;
        double m2 = g_acc[4 + k * 3 + 2] / gs;
        double a = g_acc[16 + k * 6 + 0] / gs - m0 * m0;
        double b = g_acc[16 + k * 6 + 1] / gs - m0 * m1;
        double c = g_acc[16 + k * 6 + 2] / gs - m0 * m2;
        double d = g_acc[16 + k * 6 + 3] / gs - m1 * m1;
        double e = g_acc[16 + k * 6 + 4] / gs - m1 * m2;
        double f = g_acc[16 + k * 6 + 5] / gs - m2 * m2;
        double det = a * (d * f - e * e) - b * (b * f - c * e) + c * (b * e - c * d);
        double id = 1.0 / det;
        g_si[k * 6 + 0] = (float)((d * f - e * e) * id);
        g_si[k * 6 + 1] = (float)((c * e - b * f) * id);
        g_si[k * 6 + 2] = (float)((b * e - c * d) * id);
        g_si[k * 6 + 3] = (float)((a * f - c * c) * id);
        g_si[k * 6 + 4] = (float)((b * c - a * e) * id);
        g_si[k * 6 + 5] = (float)((a * d - b * b) * id);
        g_mu[k * 3 + 0] = (float)m0;
        g_mu[k * 3 + 1] = (float)m1;
        g_mu[k * 3 + 2] = (float)m2;
        double phi = gs / (double)n;
        g_c[k] = (float)(0.5 * log(TWO_PI * TWO_PI * TWO_PI * det) - log(phi));
        double l3 = 1.0 / a + 1.0 / d + 1.0 / f;
        // accumulate loss3 across k via atomic on a double global
        atomicAdd(&g_loss3, 1e-4 * l3);
    }
    if (k == 4) g_loss3 = 0.0;   // NOTE: ordering hazard avoided below
}

// zero g_loss3 before finalize (separate tiny kernel keeps ordering safe)
__global__ void zloss_kernel() { if (threadIdx.x == 0) g_loss3 = 0.0; }

__global__ void __launch_bounds__(256) energy_kernel(float* __restrict__ out, int n) {
    __shared__ float sE[8];
    const int tid = threadIdx.x;

    // all threads read the small param set (L1/L2 broadcast)
    float mu[12], si[24], cc[4];
#pragma unroll
    for (int q = 0; q < 12; q++) mu[q] = g_mu[q];
#pragma unroll
    for (int q = 0; q < 24; q++) si[q] = g_si[q];
#pragma unroll
    for (int q = 0; q < 4; q++)  cc[q] = g_c[q];

    int i = blockIdx.x * blockDim.x + tid;
    bool v = i < n;
    int ii = v ? i : 0;
    float z0 = g_z[ii], zc = g_z[MAXN + ii], ze = g_z[2 * MAXN + ii];
    float en = 0.f;
#pragma unroll
    for (int k = 0; k < 4; k++) {
        float a = z0 - mu[k * 3 + 0];
        float b = zc - mu[k * 3 + 1];
        float c = ze - mu[k * 3 + 2];
        float q = si[k * 6 + 0] * a * a + si[k * 6 + 3] * b * b + si[k * 6 + 5] * c * c
                + 2.f * (si[k * 6 + 1] * a * b + si[k * 6 + 2] * a * c + si[k * 6 + 4] * b * c);
        en += cc[k] + 0.5f * q;
    }
    if (v) out[i] = en;

    float r = wsum(v ? en : 0.f);
    const int wid = tid >> 5, lane = tid & 31;
    if (lane == 0) sE[wid] = r;
    __syncthreads();
    if (tid == 0) {
        float t = 0.f;
#pragma unroll
        for (int w = 0; w < 8; w++) t += sE[w];
        atomicAdd(&g_acc[41], (double)t);
    }
}

__global__ void loss_kernel(float* __restrict__ out, int n, int has_loss) {
    if (threadIdx.x == 0 && has_loss) {
        double loss = g_acc[40] / (double)n + 0.01 * (g_acc[41] / (double)n) + g_loss3;
        out[n] = (float)loss;
    }
}

extern "C" void kernel_launch(void* const* d_in, const int* in_sizes, int n_in,
                              void* d_out, int out_size) {
    const float* x1  = (const float*)d_in[0];
    const float* ew1 = (const float*)d_in[1];
    const float* eb1 = (const float*)d_in[2];
    const float* ew2 = (const float*)d_in[3];
    const float* eb2 = (const float*)d_in[4];
    const float* ew3 = (const float*)d_in[5];
    const float* eb3 = (const float*)d_in[6];
    const float* dw1 = (const float*)d_in[7];
    const float* db1 = (const float*)d_in[8];
    const float* dw2 = (const float*)d_in[9];
    const float* db2 = (const float*)d_in[10];
    const float* dw3 = (const float*)d_in[11];
    const float* db3 = (const float*)d_in[12];
    const float* tw1 = (const float*)d_in[13];
    const float* tb1 = (const float*)d_in[14];
    const float* tw2 = (const float*)d_in[15];
    const float* tb2 = (const float*)d_in[16];

    int n = in_sizes[0] / 128;
    if (n > MAXN) n = MAXN;
    float* out = (float*)d_out;

    zloss_kernel<<<1, 32>>>();
    prep_kernel<<<1, 256>>>(dw3, db3);     // also zeroes g_acc
    int blocks = (n + TPB - 1) / TPB;
    fwd_kernel<<<blocks, TPB>>>(x1, ew1, eb1, ew2, eb2, ew3, eb3,
                                dw1, db1, dw2, db2, dw3, db3,
                                tw1, tb1, tw2, tb2, n);
    finalize_kernel<<<1, 32>>>(n);
    energy_kernel<<<(n + 255) / 256, 256>>>(out, n);
    loss_kernel<<<1, 32>>>(out, n, out_size > n ? 1 : 0);
}